// round 13
// baseline (speedup 1.0000x reference)
#include <cuda_runtime.h>
#include <cuda_fp16.h>
#include <cstdint>
#include <math.h>

#define NHEADS 12
#define NWIN   1152
#define NTOK   64
#define CDIM   384
#define DH     32
#define MROWS  (NWIN * NTOK)   // 73728

typedef unsigned long long ull;

// ---------------------------------------------------------------------------
// Device-global scratch
// ---------------------------------------------------------------------------
__device__ float g_Q [MROWS * CDIM];
__device__ float g_K [MROWS * CDIM];
__device__ float g_V [MROWS * CDIM];
__device__ float g_tb[225 * NHEADS];   // 16*sigmoid(cpb) precomputed
__device__ float g_ls[NHEADS];
__device__ float g_bcat[3 * CDIM];

__device__ __half g_Ahi[MROWS * CDIM];
__device__ __half g_Alo[MROWS * CDIM];
__device__ __half g_W[CDIM * 1536];

// ---------------------------------------------------------------------------
// helpers
// ---------------------------------------------------------------------------
__device__ __forceinline__ uint32_t smem_u32(const void* p)
{
    uint32_t a;
    asm("{ .reg .u64 t; cvta.to.shared.u64 t, %1; cvt.u32.u64 %0, t; }" : "=r"(a) : "l"(p));
    return a;
}
__device__ __forceinline__ void ldsm_x4(uint32_t r[4], uint32_t addr)
{
    asm volatile("ldmatrix.sync.aligned.m8n8.x4.shared.b16 {%0,%1,%2,%3}, [%4];"
                 : "=r"(r[0]), "=r"(r[1]), "=r"(r[2]), "=r"(r[3]) : "r"(addr));
}
__device__ __forceinline__ void ldsm_x4_t(uint32_t r[4], uint32_t addr)
{
    asm volatile("ldmatrix.sync.aligned.m8n8.x4.trans.shared.b16 {%0,%1,%2,%3}, [%4];"
                 : "=r"(r[0]), "=r"(r[1]), "=r"(r[2]), "=r"(r[3]) : "r"(addr));
}
__device__ __forceinline__ void mma_f16(float c[4], const uint32_t a[4], const uint32_t b[2])
{
    asm volatile(
        "mma.sync.aligned.m16n8k16.row.col.f32.f16.f16.f32 "
        "{%0,%1,%2,%3},{%4,%5,%6,%7},{%8,%9},{%0,%1,%2,%3};"
        : "+f"(c[0]), "+f"(c[1]), "+f"(c[2]), "+f"(c[3])
        : "r"(a[0]), "r"(a[1]), "r"(a[2]), "r"(a[3]), "r"(b[0]), "r"(b[1]));
}

// f32x2 packed helpers
__device__ __forceinline__ ull fma2(ull a, ull b, ull c)
{
    ull d; asm("fma.rn.f32x2 %0, %1, %2, %3;" : "=l"(d) : "l"(a), "l"(b), "l"(c)); return d;
}
__device__ __forceinline__ ull add2(ull a, ull b)
{
    ull d; asm("add.rn.f32x2 %0, %1, %2;" : "=l"(d) : "l"(a), "l"(b)); return d;
}
__device__ __forceinline__ ull pk2(float lo, float hi)
{
    ull r; asm("mov.b64 %0, {%1, %2};" : "=l"(r) : "f"(lo), "f"(hi)); return r;
}
__device__ __forceinline__ float2 upk2(ull v)
{
    float lo, hi; asm("mov.b64 {%0, %1}, %2;" : "=f"(lo), "=f"(hi) : "l"(v)); return make_float2(lo, hi);
}

// ---------------------------------------------------------------------------
// Kernel 0a: fp32 -> (fp16 hi, fp16 lo) split
// ---------------------------------------------------------------------------
__global__ void convert_split_kernel(const float* __restrict__ src,
                                     __half* __restrict__ hi,
                                     __half* __restrict__ lo, int n4)
{
    int i = blockIdx.x * blockDim.x + threadIdx.x;
    if (i >= n4) return;
    float4 v = reinterpret_cast<const float4*>(src)[i];
    float vv[4] = {v.x, v.y, v.z, v.w};
    __align__(8) __half h[4], l[4];
    #pragma unroll
    for (int j = 0; j < 4; j++) {
        h[j] = __float2half_rn(vv[j]);
        l[j] = __float2half_rn(vv[j] - __half2float(h[j]));
    }
    reinterpret_cast<uint2*>(hi)[i] = *reinterpret_cast<uint2*>(h);
    reinterpret_cast<uint2*>(lo)[i] = *reinterpret_cast<uint2*>(l);
}

// ---------------------------------------------------------------------------
// Kernel 0b: W[k][n] fp32 -> fp16 plane at column offset
// ---------------------------------------------------------------------------
__global__ void w_fp16_kernel(const float* __restrict__ src,
                              __half* __restrict__ dst,
                              int ncols, int coloff)
{
    int i = blockIdx.x * blockDim.x + threadIdx.x;
    if (i >= 36864) return;
    int k  = i / 96;
    int n4 = (i % 96) * 4;
    float4 v = *reinterpret_cast<const float4*>(&src[(size_t)k * 384 + n4]);
    __align__(8) __half h[4];
    h[0] = __float2half_rn(v.x);
    h[1] = __float2half_rn(v.y);
    h[2] = __float2half_rn(v.z);
    h[3] = __float2half_rn(v.w);
    size_t o = (size_t)k * ncols + coloff + n4;
    *reinterpret_cast<uint2*>(&dst[o]) = *reinterpret_cast<uint2*>(h);
}

__global__ void bias_cat_kernel(const float* __restrict__ bq, const float* __restrict__ bv)
{
    int i = blockIdx.x * blockDim.x + threadIdx.x;
    if (i >= 1152) return;
    g_bcat[i] = (i < 384) ? bq[i] : ((i < 768) ? 0.f : bv[i - 768]);
}

// ---------------------------------------------------------------------------
// Kernel 1: continuous position bias MLP (stores 16*sigmoid directly)
// ---------------------------------------------------------------------------
__global__ void cpb_kernel(const float* __restrict__ w1, const float* __restrict__ b1,
                           const float* __restrict__ w2, const float* __restrict__ b2,
                           const float* __restrict__ tau)
{
    __shared__ float red[128][12];
    const int m   = blockIdx.x;
    const int tid = threadIdx.x;
    const int ai  = m / 15;
    const int bi  = m % 15;

    float x0 = (float)(bi - 7) * (8.0f / 7.0f);
    float x1 = (float)(ai - 7) * (8.0f / 7.0f);
    float s0 = (x0 > 0.f) ? 1.f : ((x0 < 0.f) ? -1.f : 0.f);
    float s1 = (x1 > 0.f) ? 1.f : ((x1 < 0.f) ? -1.f : 0.f);
    float v0 = s0 * log2f(fabsf(x0) + 1.0f) * (1.0f / 3.0f);
    float v1 = s1 * log2f(fabsf(x1) + 1.0f) * (1.0f / 3.0f);

    float p[NHEADS];
    #pragma unroll
    for (int h = 0; h < NHEADS; h++) p[h] = 0.f;

    for (int c = tid; c < 512; c += 128) {
        float hv = v0 * w1[c] + v1 * w1[512 + c] + b1[c];
        hv = fmaxf(hv, 0.0f);
        #pragma unroll
        for (int h = 0; h < NHEADS; h++) p[h] += hv * w2[c * NHEADS + h];
    }
    #pragma unroll
    for (int h = 0; h < NHEADS; h++) red[tid][h] = p[h];
    __syncthreads();

    if (tid < NHEADS) {
        float s = 0.f;
        for (int t2 = 0; t2 < 128; t2++) s += red[t2][tid];
        float v = s + b2[tid];
        g_tb[m * NHEADS + tid] = 16.0f / (1.0f + expf(-v));
        if (m == 0) g_ls[tid] = fmaxf(tau[tid] + 2.302585092994046f, 0.01f);
    }
}

// ---------------------------------------------------------------------------
// Kernel 2: double-buffered 2-term fp16 GEMM (unchanged from round 11)
// ---------------------------------------------------------------------------
__global__ __launch_bounds__(256, 2) void gemm_db_kernel(
    const __half* __restrict__ Ahi, const __half* __restrict__ Alo,
    const __half* __restrict__ W,
    const float* __restrict__ bias,
    float* C0, float* C1, float* C2, int Ntot)
{
    __shared__ __align__(16) __half As[2][128][40];
    __shared__ __align__(16) __half Bs[2][32][136];

    const int tid  = threadIdx.x;
    const int lane = tid & 31;
    const int warp = tid >> 5;
    const int wm   = warp >> 2;
    const int wn   = warp & 3;
    const int rb   = blockIdx.y * 128;
    const int cb   = blockIdx.x * 128;
    const int gid  = cb / 384;
    float* C = (gid == 0) ? C0 : ((gid == 1) ? C1 : C2);

    const int ar = tid >> 1;
    const int ac = (tid & 1) * 16;
    const int br = tid >> 3;
    const int bc = (tid & 7) * 16;

    const int g  = lane >> 3;
    const int lr = lane & 7;
    const int a_row  = wm * 64 + lr + (g & 1) * 8;
    const int a_col  = (g >> 1) * 8;
    const int b_krow = lr + (g & 1) * 8;
    const int b_ncol = wn * 32 + (g >> 1) * 8;

    float acc[4][4][4];
    #pragma unroll
    for (int mi = 0; mi < 4; mi++)
        #pragma unroll
        for (int ni = 0; ni < 4; ni++)
            #pragma unroll
            for (int q = 0; q < 4; q++) acc[mi][ni][q] = 0.f;

    int4 aR0, aR1, bR0, bR1;
    {
        const __half* ga = &Ahi[(size_t)(rb + ar) * 384 + ac];
        aR0 = *reinterpret_cast<const int4*>(ga);
        aR1 = *reinterpret_cast<const int4*>(ga + 8);
        const __half* gb = &W[(size_t)br * Ntot + cb + bc];
        bR0 = *reinterpret_cast<const int4*>(gb);
        bR1 = *reinterpret_cast<const int4*>(gb + 8);
    }

    const uint32_t asb = smem_u32(&As[0][0][0]);
    const uint32_t bsb = smem_u32(&Bs[0][0][0]);

    for (int c = 0; c < 24; c++) {
        const int buf = c & 1;
        *reinterpret_cast<int4*>(&As[buf][ar][ac])     = aR0;
        *reinterpret_cast<int4*>(&As[buf][ar][ac + 8]) = aR1;
        *reinterpret_cast<int4*>(&Bs[buf][br][bc])     = bR0;
        *reinterpret_cast<int4*>(&Bs[buf][br][bc + 8]) = bR1;
        __syncthreads();

        if (c + 1 < 24) {
            const int nc   = c + 1;
            const int kl   = (nc % 12) * 32;
            const __half* pA = (nc < 12) ? Ahi : Alo;
            const __half* ga = &pA[(size_t)(rb + ar) * 384 + kl + ac];
            aR0 = *reinterpret_cast<const int4*>(ga);
            aR1 = *reinterpret_cast<const int4*>(ga + 8);
            const __half* gb = &W[(size_t)(kl + br) * Ntot + cb + bc];
            bR0 = *reinterpret_cast<const int4*>(gb);
            bR1 = *reinterpret_cast<const int4*>(gb + 8);
        }

        const uint32_t sA = asb + buf * 10240;
        const uint32_t sB = bsb + buf * 8704;
        #pragma unroll
        for (int ks = 0; ks < 2; ks++) {
            uint32_t af[4][4];
            #pragma unroll
            for (int mi = 0; mi < 4; mi++)
                ldsm_x4(af[mi], sA + ((a_row + mi * 16) * 40 + ks * 16 + a_col) * 2);
            uint32_t bf_[2][4];
            #pragma unroll
            for (int nt = 0; nt < 2; nt++)
                ldsm_x4_t(bf_[nt], sB + ((ks * 16 + b_krow) * 136 + b_ncol + nt * 16) * 2);
            #pragma unroll
            for (int mi = 0; mi < 4; mi++)
                #pragma unroll
                for (int ni = 0; ni < 4; ni++)
                    mma_f16(acc[mi][ni], af[mi], &bf_[ni >> 1][(ni & 1) * 2]);
        }
    }

    #pragma unroll
    for (int mi = 0; mi < 4; mi++) {
        #pragma unroll
        for (int ni = 0; ni < 4; ni++) {
            int r    = rb + wm * 64 + mi * 16 + (lane >> 2);
            int ccat = cb + wn * 32 + ni * 8 + (lane & 3) * 2;
            int cc   = ccat - gid * 384;
            float b0 = bias[ccat];
            float b1 = bias[ccat + 1];
            float2 v0 = make_float2(acc[mi][ni][0] + b0, acc[mi][ni][1] + b1);
            float2 v1 = make_float2(acc[mi][ni][2] + b0, acc[mi][ni][3] + b1);
            *reinterpret_cast<float2*>(&C[(size_t)r * 384 + cc])       = v0;
            *reinterpret_cast<float2*>(&C[(size_t)(r + 8) * 384 + cc]) = v1;
        }
    }
}

// ---------------------------------------------------------------------------
// Kernel 3: attention with row-pairing + skewed K loads (conflict-free).
// Thread = (rows i0 = tid>>2 and i0+32, col/dim quarter cq = tid&3).
// Mask pre-staged into at[] during load phase. grid (1152,12), block 128.
// ---------------------------------------------------------------------------
__global__ __launch_bounds__(128) void attn_kernel(const float* __restrict__ mask)
{
    __shared__ float qs [NTOK * DH];
    __shared__ float kss[NTOK * DH];
    __shared__ float vss[NTOK * DH];
    __shared__ float at [NTOK * 65];
    __shared__ float qn [NTOK];
    __shared__ float kn [NTOK];
    __shared__ float tbs[225];

    const int b   = blockIdx.x;
    const int h   = blockIdx.y;
    const int tid = threadIdx.x;
    const size_t base = (size_t)b * NTOK * CDIM + h * DH;

    for (int idx = tid; idx < 512; idx += 128) {
        int n = idx >> 3;
        int d = (idx & 7) << 2;
        size_t ga = base + (size_t)n * CDIM + d;
        *reinterpret_cast<float4*>(&qs [n * DH + d]) = *reinterpret_cast<const float4*>(&g_Q[ga]);
        *reinterpret_cast<float4*>(&kss[n * DH + d]) = *reinterpret_cast<const float4*>(&g_K[ga]);
        *reinterpret_cast<float4*>(&vss[n * DH + d]) = *reinterpret_cast<const float4*>(&g_V[ga]);
    }
    for (int i = tid; i < 225; i += 128) tbs[i] = g_tb[i * NHEADS + h];
    // pre-stage mask into at (coalesced reads; at unused until logits)
    {
        const float4* mp = reinterpret_cast<const float4*>(mask + (size_t)b * 4096);
        for (int idx = tid; idx < 1024; idx += 128) {
            float4 mv = mp[idx];
            int f = idx << 2;
            int i = f >> 6, j = f & 63;
            at[i * 65 + j]     = mv.x;
            at[i * 65 + j + 1] = mv.y;
            at[i * 65 + j + 2] = mv.z;
            at[i * 65 + j + 3] = mv.w;
        }
    }
    const float ls = g_ls[h];
    __syncthreads();

    // norms
    {
        const float* src = (tid < 64) ? qs : kss;
        int i = (tid < 64) ? tid : (tid - 64);
        const ulonglong2* p = reinterpret_cast<const ulonglong2*>(&src[i * DH]);
        ull a0 = 0ull, a1 = 0ull;
        #pragma unroll
        for (int u = 0; u < 8; u++) {
            ulonglong2 v = p[u];
            a0 = fma2(v.x, v.x, a0);
            a1 = fma2(v.y, v.y, a1);
        }
        float2 s2 = upk2(add2(a0, a1));
        float nrm = sqrtf(s2.x + s2.y);
        if (tid < 64) qn[i] = nrm; else kn[i] = nrm;
    }
    __syncthreads();

    const int i0 = tid >> 2;        // 0..31
    const int i1 = i0 + 32;
    const int cq = tid & 3;

    // ---- logits: 2 rows x 16 cols per thread, skewed K loads ----
    {
        ull q0[16], q1[16];
        {
            const ulonglong2* p0 = reinterpret_cast<const ulonglong2*>(&qs[i0 * DH]);
            const ulonglong2* p1 = reinterpret_cast<const ulonglong2*>(&qs[i1 * DH]);
            #pragma unroll
            for (int u = 0; u < 8; u++) {
                ulonglong2 v0 = p0[u]; q0[2 * u] = v0.x; q0[2 * u + 1] = v0.y;
                ulonglong2 v1 = p1[u]; q1[2 * u] = v1.x; q1[2 * u + 1] = v1.y;
            }
        }
        const float qn0 = qn[i0], qn1 = qn[i1];
        const int r0 = i0 >> 3, c0 = i0 & 7;
        const int r1 = i1 >> 3, c1 = i1 & 7;
        const int sk = cq * 2;      // bank-quad skew per cq group

        #pragma unroll 4
        for (int jj = 0; jj < 16; jj++) {
            const int j = cq * 16 + jj;
            const ulonglong2* kp = reinterpret_cast<const ulonglong2*>(&kss[j * DH]);
            ull a0 = 0ull, a1 = 0ull, c0a = 0ull, c1a = 0ull;
            #pragma unroll
            for (int s = 0; s < 8; s++) {
                const int u = (s + sk) & 7;
                ulonglong2 kv = kp[u];
                a0  = fma2(q0[2 * u],     kv.x, a0);
                a1  = fma2(q0[2 * u + 1], kv.y, a1);
                c0a = fma2(q1[2 * u],     kv.x, c0a);
                c1a = fma2(q1[2 * u + 1], kv.y, c1a);
            }
            float2 sa = upk2(add2(a0, a1));
            float2 sb = upk2(add2(c0a, c1a));
            float dot0 = sa.x + sa.y;
            float dot1 = sb.x + sb.y;
            const float knj = kn[j];
            const int rj = j >> 3, cj = j & 7;
            int idx0 = ((r0 - rj) + 7) * 15 + (c0 - cj) + 7;
            int idx1 = ((r1 - rj) + 7) * 15 + (c1 - cj) + 7;
            float f0 = __fdividef(ls, fmaxf(qn0 * knj, 1e-6f));
            float f1 = __fdividef(ls, fmaxf(qn1 * knj, 1e-6f));
            at[i0 * 65 + j] = dot0 * f0 + tbs[idx0] + at[i0 * 65 + j];
            at[i1 * 65 + j] = dot1 * f1 + tbs[idx1] + at[i1 * 65 + j];
        }
    }
    __syncthreads();

    // softmax per row
    if (tid < 64) {
        float* row = &at[tid * 65];
        float m = row[0];
        #pragma unroll 8
        for (int j = 1; j < 64; j++) m = fmaxf(m, row[j]);
        float s = 0.f;
        #pragma unroll 8
        for (int j = 0; j < 64; j++) { float e = __expf(row[j] - m); row[j] = e; s += e; }
        float inv = 1.0f / s;
        #pragma unroll 8
        for (int j = 0; j < 64; j++) row[j] *= inv;
    }
    __syncthreads();

    // ---- AV: 2 rows x 8 d-cols per thread, V loads shared across rows ----
    {
        const int d0 = cq * 8;
        ull acc0[4], acc1[4];
        #pragma unroll
        for (int u = 0; u < 4; u++) { acc0[u] = 0ull; acc1[u] = 0ull; }
        const float* pr0 = &at[i0 * 65];
        const float* pr1 = &at[i1 * 65];
        #pragma unroll 4
        for (int j = 0; j < 64; j++) {
            const ulonglong2* vp = reinterpret_cast<const ulonglong2*>(&vss[j * DH + d0]);
            ulonglong2 v = vp[0], v2 = vp[1];
            float p0 = pr0[j], p1 = pr1[j];
            ull pp0 = pk2(p0, p0);
            ull pp1 = pk2(p1, p1);
            acc0[0] = fma2(pp0, v.x,  acc0[0]);
            acc0[1] = fma2(pp0, v.y,  acc0[1]);
            acc0[2] = fma2(pp0, v2.x, acc0[2]);
            acc0[3] = fma2(pp0, v2.y, acc0[3]);
            acc1[0] = fma2(pp1, v.x,  acc1[0]);
            acc1[1] = fma2(pp1, v.y,  acc1[1]);
            acc1[2] = fma2(pp1, v2.x, acc1[2]);
            acc1[3] = fma2(pp1, v2.y, acc1[3]);
        }
        #pragma unroll
        for (int rr = 0; rr < 2; rr++) {
            ull* ac = rr ? acc1 : acc0;
            int  ii = rr ? i1 : i0;
            __align__(16) __half hh[8], ll[8];
            #pragma unroll
            for (int u = 0; u < 4; u++) {
                float2 f = upk2(ac[u]);
                __half h0 = __float2half_rn(f.x);
                __half h1 = __float2half_rn(f.y);
                hh[2 * u]     = h0;
                hh[2 * u + 1] = h1;
                ll[2 * u]     = __float2half_rn(f.x - __half2float(h0));
                ll[2 * u + 1] = __float2half_rn(f.y - __half2float(h1));
            }
            size_t ob = (size_t)(b * NTOK + ii) * CDIM + h * DH + d0;
            *reinterpret_cast<uint4*>(&g_Ahi[ob]) = *reinterpret_cast<uint4*>(hh);
            *reinterpret_cast<uint4*>(&g_Alo[ob]) = *reinterpret_cast<uint4*>(ll);
        }
    }
}

// ---------------------------------------------------------------------------
// Launch
// ---------------------------------------------------------------------------
extern "C" void kernel_launch(void* const* d_in, const int* in_sizes, int n_in,
                              void* d_out, int out_size)
{
    (void)in_sizes; (void)n_in; (void)out_size;
    const float* x     = (const float*)d_in[0];
    const float* mask  = (const float*)d_in[1];
    const float* wq    = (const float*)d_in[2];
    const float* bq    = (const float*)d_in[3];
    const float* wk    = (const float*)d_in[4];
    const float* wv    = (const float*)d_in[5];
    const float* bv    = (const float*)d_in[6];
    const float* cw1   = (const float*)d_in[7];
    const float* cb1   = (const float*)d_in[8];
    const float* cw2   = (const float*)d_in[9];
    const float* cb2   = (const float*)d_in[10];
    const float* tau   = (const float*)d_in[11];
    const float* wproj = (const float*)d_in[12];
    const float* bproj = (const float*)d_in[13];
    float* out = (float*)d_out;

    float *pQ, *pK, *pV, *pBcat;
    __half *pAhi, *pAlo, *pW;
    cudaGetSymbolAddress((void**)&pQ,    g_Q);
    cudaGetSymbolAddress((void**)&pK,    g_K);
    cudaGetSymbolAddress((void**)&pV,    g_V);
    cudaGetSymbolAddress((void**)&pBcat, g_bcat);
    cudaGetSymbolAddress((void**)&pAhi,  g_Ahi);
    cudaGetSymbolAddress((void**)&pAlo,  g_Alo);
    cudaGetSymbolAddress((void**)&pW,    g_W);

    const int xn4 = MROWS * CDIM / 4;
    const int PROJ_OFF = CDIM * 1152;

    convert_split_kernel<<<(xn4 + 255) / 256, 256>>>(x, pAhi, pAlo, xn4);
    w_fp16_kernel<<<144, 256>>>(wq, pW, 1152, 0);
    w_fp16_kernel<<<144, 256>>>(wk, pW, 1152, 384);
    w_fp16_kernel<<<144, 256>>>(wv, pW, 1152, 768);
    bias_cat_kernel<<<5, 256>>>(bq, bv);

    gemm_db_kernel<<<dim3(9, MROWS / 128), 256>>>(
        pAhi, pAlo, pW, pBcat, pQ, pK, pV, 1152);

    cpb_kernel<<<225, 128>>>(cw1, cb1, cw2, cb2, tau);
    attn_kernel<<<dim3(NWIN, NHEADS), 128>>>(mask);

    w_fp16_kernel<<<144, 256>>>(wproj, pW + PROJ_OFF, 384, 0);
    gemm_db_kernel<<<dim3(3, MROWS / 128), 256>>>(
        pAhi, pAlo, pW + PROJ_OFF, bproj, out, nullptr, nullptr, 384);
}

// round 14
// speedup vs baseline: 1.1533x; 1.1533x over previous
#include <cuda_runtime.h>
#include <cuda_fp16.h>
#include <cstdint>
#include <math.h>

#define NHEADS 12
#define NWIN   1152
#define NTOK   64
#define CDIM   384
#define DH     32
#define MROWS  (NWIN * NTOK)   // 73728

typedef unsigned long long ull;

// ---------------------------------------------------------------------------
// Device-global scratch
// ---------------------------------------------------------------------------
__device__ __half g_Qh[MROWS * CDIM];
__device__ __half g_Kh[MROWS * CDIM];
__device__ __half g_Vh[MROWS * CDIM];
__device__ float g_tb[225 * NHEADS];   // 16*sigmoid(cpb) precomputed
__device__ float g_ls[NHEADS];
__device__ float g_bcat[3 * CDIM];

__device__ __half g_Ahi[MROWS * CDIM];
__device__ __half g_Alo[MROWS * CDIM];
__device__ __half g_W[CDIM * 1536];

// ---------------------------------------------------------------------------
// helpers
// ---------------------------------------------------------------------------
__device__ __forceinline__ uint32_t smem_u32(const void* p)
{
    uint32_t a;
    asm("{ .reg .u64 t; cvta.to.shared.u64 t, %1; cvt.u32.u64 %0, t; }" : "=r"(a) : "l"(p));
    return a;
}
__device__ __forceinline__ void cp16(uint32_t dst, const void* src)
{
    asm volatile("cp.async.cg.shared.global [%0], [%1], 16;" :: "r"(dst), "l"(src));
}
#define CP_COMMIT() asm volatile("cp.async.commit_group;" ::: "memory")
#define CP_WAIT1()  asm volatile("cp.async.wait_group 1;" ::: "memory")
#define CP_WAIT0()  asm volatile("cp.async.wait_group 0;" ::: "memory")

__device__ __forceinline__ void ldsm_x4(uint32_t r[4], uint32_t addr)
{
    asm volatile("ldmatrix.sync.aligned.m8n8.x4.shared.b16 {%0,%1,%2,%3}, [%4];"
                 : "=r"(r[0]), "=r"(r[1]), "=r"(r[2]), "=r"(r[3]) : "r"(addr));
}
__device__ __forceinline__ void ldsm_x4_t(uint32_t r[4], uint32_t addr)
{
    asm volatile("ldmatrix.sync.aligned.m8n8.x4.trans.shared.b16 {%0,%1,%2,%3}, [%4];"
                 : "=r"(r[0]), "=r"(r[1]), "=r"(r[2]), "=r"(r[3]) : "r"(addr));
}
__device__ __forceinline__ void mma_f16(float c[4], const uint32_t a[4], const uint32_t b[2])
{
    asm volatile(
        "mma.sync.aligned.m16n8k16.row.col.f32.f16.f16.f32 "
        "{%0,%1,%2,%3},{%4,%5,%6,%7},{%8,%9},{%0,%1,%2,%3};"
        : "+f"(c[0]), "+f"(c[1]), "+f"(c[2]), "+f"(c[3])
        : "r"(a[0]), "r"(a[1]), "r"(a[2]), "r"(a[3]), "r"(b[0]), "r"(b[1]));
}

// f32x2 packed helpers
__device__ __forceinline__ ull fma2(ull a, ull b, ull c)
{
    ull d; asm("fma.rn.f32x2 %0, %1, %2, %3;" : "=l"(d) : "l"(a), "l"(b), "l"(c)); return d;
}
__device__ __forceinline__ ull add2(ull a, ull b)
{
    ull d; asm("add.rn.f32x2 %0, %1, %2;" : "=l"(d) : "l"(a), "l"(b)); return d;
}
__device__ __forceinline__ ull pk2(float lo, float hi)
{
    ull r; asm("mov.b64 %0, {%1, %2};" : "=l"(r) : "f"(lo), "f"(hi)); return r;
}
__device__ __forceinline__ float2 upk2(ull v)
{
    float lo, hi; asm("mov.b64 {%0, %1}, %2;" : "=f"(lo), "=f"(hi) : "l"(v)); return make_float2(lo, hi);
}

// ---------------------------------------------------------------------------
// Kernel 0a: fp32 -> (fp16 hi, fp16 lo) split
// ---------------------------------------------------------------------------
__global__ void convert_split_kernel(const float* __restrict__ src,
                                     __half* __restrict__ hi,
                                     __half* __restrict__ lo, int n4)
{
    int i = blockIdx.x * blockDim.x + threadIdx.x;
    if (i >= n4) return;
    float4 v = reinterpret_cast<const float4*>(src)[i];
    float vv[4] = {v.x, v.y, v.z, v.w};
    __align__(8) __half h[4], l[4];
    #pragma unroll
    for (int j = 0; j < 4; j++) {
        h[j] = __float2half_rn(vv[j]);
        l[j] = __float2half_rn(vv[j] - __half2float(h[j]));
    }
    reinterpret_cast<uint2*>(hi)[i] = *reinterpret_cast<uint2*>(h);
    reinterpret_cast<uint2*>(lo)[i] = *reinterpret_cast<uint2*>(l);
}

// ---------------------------------------------------------------------------
// Kernel 0b: W[k][n] fp32 -> fp16 plane at column offset
// ---------------------------------------------------------------------------
__global__ void w_fp16_kernel(const float* __restrict__ src,
                              __half* __restrict__ dst,
                              int ncols, int coloff)
{
    int i = blockIdx.x * blockDim.x + threadIdx.x;
    if (i >= 36864) return;
    int k  = i / 96;
    int n4 = (i % 96) * 4;
    float4 v = *reinterpret_cast<const float4*>(&src[(size_t)k * 384 + n4]);
    __align__(8) __half h[4];
    h[0] = __float2half_rn(v.x);
    h[1] = __float2half_rn(v.y);
    h[2] = __float2half_rn(v.z);
    h[3] = __float2half_rn(v.w);
    size_t o = (size_t)k * ncols + coloff + n4;
    *reinterpret_cast<uint2*>(&dst[o]) = *reinterpret_cast<uint2*>(h);
}

__global__ void bias_cat_kernel(const float* __restrict__ bq, const float* __restrict__ bv)
{
    int i = blockIdx.x * blockDim.x + threadIdx.x;
    if (i >= 1152) return;
    g_bcat[i] = (i < 384) ? bq[i] : ((i < 768) ? 0.f : bv[i - 768]);
}

// ---------------------------------------------------------------------------
// Kernel 1: continuous position bias MLP (stores 16*sigmoid directly)
// ---------------------------------------------------------------------------
__global__ void cpb_kernel(const float* __restrict__ w1, const float* __restrict__ b1,
                           const float* __restrict__ w2, const float* __restrict__ b2,
                           const float* __restrict__ tau)
{
    __shared__ float red[128][12];
    const int m   = blockIdx.x;
    const int tid = threadIdx.x;
    const int ai  = m / 15;
    const int bi  = m % 15;

    float x0 = (float)(bi - 7) * (8.0f / 7.0f);
    float x1 = (float)(ai - 7) * (8.0f / 7.0f);
    float s0 = (x0 > 0.f) ? 1.f : ((x0 < 0.f) ? -1.f : 0.f);
    float s1 = (x1 > 0.f) ? 1.f : ((x1 < 0.f) ? -1.f : 0.f);
    float v0 = s0 * log2f(fabsf(x0) + 1.0f) * (1.0f / 3.0f);
    float v1 = s1 * log2f(fabsf(x1) + 1.0f) * (1.0f / 3.0f);

    float p[NHEADS];
    #pragma unroll
    for (int h = 0; h < NHEADS; h++) p[h] = 0.f;

    for (int c = tid; c < 512; c += 128) {
        float hv = v0 * w1[c] + v1 * w1[512 + c] + b1[c];
        hv = fmaxf(hv, 0.0f);
        #pragma unroll
        for (int h = 0; h < NHEADS; h++) p[h] += hv * w2[c * NHEADS + h];
    }
    #pragma unroll
    for (int h = 0; h < NHEADS; h++) red[tid][h] = p[h];
    __syncthreads();

    if (tid < NHEADS) {
        float s = 0.f;
        for (int t2 = 0; t2 < 128; t2++) s += red[t2][tid];
        float v = s + b2[tid];
        g_tb[m * NHEADS + tid] = 16.0f / (1.0f + expf(-v));
        if (m == 0) g_ls[tid] = fmaxf(tau[tid] + 2.302585092994046f, 0.01f);
    }
}

// ---------------------------------------------------------------------------
// Kernel 2: 3-stage cp.async fp16 GEMM, K-chunk 64 (12 chunks).
// C = (Ahi + Alo) @ W (+bias). Block tile 128x128, 8 warps (2x4), warp 64x32.
// half_out: C arrays are __half (QKV); else float (proj/out).
// dynamic smem = 3 * (128*72 + 64*136) * 2 = 107520 B
// ---------------------------------------------------------------------------
#define A_BYTES 18432            // 128 rows x 72 halves (144 B rows)
#define B_BYTES 17408            // 64 rows x 136 halves (272 B rows)
#define STG_BYTES (A_BYTES + B_BYTES)        // 35840
#define GEMM_SMEM (3 * STG_BYTES)            // 107520

__global__ __launch_bounds__(256, 2) void gemm_cp_kernel(
    const __half* __restrict__ Ahi, const __half* __restrict__ Alo,
    const __half* __restrict__ W,
    const float* __restrict__ bias,
    void* C0, void* C1, void* C2, int Ntot, int half_out)
{
    extern __shared__ __align__(128) char smem[];
    const uint32_t sb = smem_u32(smem);
    const int tid  = threadIdx.x;
    const int lane = tid & 31;
    const int warp = tid >> 5;
    const int wm   = warp >> 2;        // 0..1
    const int wn   = warp & 3;         // 0..3
    const int rb   = blockIdx.y * 128;
    const int cb   = blockIdx.x * 128;
    const int gid  = cb / 384;
    void* C = (gid == 0) ? C0 : ((gid == 1) ? C1 : C2);

    const int g  = lane >> 3;
    const int lr = lane & 7;
    const int a_row  = wm * 64 + lr + (g & 1) * 8;
    const int a_col  = (g >> 1) * 8;
    const int b_krow = lr + (g & 1) * 8;
    const int b_ncol = wn * 32 + (g >> 1) * 8;

    float acc[4][4][4];
    #pragma unroll
    for (int mi = 0; mi < 4; mi++)
        #pragma unroll
        for (int ni = 0; ni < 4; ni++)
            #pragma unroll
            for (int q = 0; q < 4; q++) acc[mi][ni][q] = 0.f;

    // stage chunk c (64 k-cols) into ring buffer buf
    auto stage = [&](int c, int buf) {
        const int kl = (c % 6) * 64;
        const __half* pA = (c < 6) ? Ahi : Alo;
        const uint32_t st = sb + buf * STG_BYTES;
        #pragma unroll
        for (int i = 0; i < 4; i++) {
            int id = tid + i * 256;          // 0..1023
            int r  = id >> 3;                // 0..127
            int cc = id & 7;                 // 16B units within row
            cp16(st + r * 144 + cc * 16,
                 &pA[(size_t)(rb + r) * 384 + kl + cc * 8]);
        }
        #pragma unroll
        for (int i = 0; i < 4; i++) {
            int id = tid + i * 256;
            int r  = id >> 4;                // 0..63
            int cc = id & 15;
            cp16(st + A_BYTES + r * 272 + cc * 16,
                 &W[(size_t)(kl + r) * Ntot + cb + cc * 8]);
        }
    };

    stage(0, 0); CP_COMMIT();
    stage(1, 1); CP_COMMIT();

    for (int c = 0; c < 12; c++) {
        if (c < 11) CP_WAIT1(); else CP_WAIT0();
        __syncthreads();
        if (c + 2 < 12) { stage(c + 2, (c + 2) % 3); CP_COMMIT(); }

        const uint32_t sA = sb + (c % 3) * STG_BYTES;
        const uint32_t sB = sA + A_BYTES;
        #pragma unroll
        for (int ks = 0; ks < 4; ks++) {
            uint32_t af[4][4];
            #pragma unroll
            for (int mi = 0; mi < 4; mi++)
                ldsm_x4(af[mi], sA + ((a_row + mi * 16) * 72 + ks * 16 + a_col) * 2);
            uint32_t bf_[2][4];
            #pragma unroll
            for (int nt = 0; nt < 2; nt++)
                ldsm_x4_t(bf_[nt], sB + ((ks * 16 + b_krow) * 136 + b_ncol + nt * 16) * 2);
            #pragma unroll
            for (int mi = 0; mi < 4; mi++)
                #pragma unroll
                for (int ni = 0; ni < 4; ni++)
                    mma_f16(acc[mi][ni], af[mi], &bf_[ni >> 1][(ni & 1) * 2]);
        }
    }

    // epilogue
    #pragma unroll
    for (int mi = 0; mi < 4; mi++) {
        #pragma unroll
        for (int ni = 0; ni < 4; ni++) {
            int r    = rb + wm * 64 + mi * 16 + (lane >> 2);
            int ccat = cb + wn * 32 + ni * 8 + (lane & 3) * 2;
            int cc   = ccat - gid * 384;
            float b0 = bias[ccat];
            float b1 = bias[ccat + 1];
            float o00 = acc[mi][ni][0] + b0, o01 = acc[mi][ni][1] + b1;
            float o10 = acc[mi][ni][2] + b0, o11 = acc[mi][ni][3] + b1;
            if (half_out) {
                __half* Ch = (__half*)C;
                *reinterpret_cast<__half2*>(&Ch[(size_t)r * 384 + cc])       = __floats2half2_rn(o00, o01);
                *reinterpret_cast<__half2*>(&Ch[(size_t)(r + 8) * 384 + cc]) = __floats2half2_rn(o10, o11);
            } else {
                float* Cf = (float*)C;
                *reinterpret_cast<float2*>(&Cf[(size_t)r * 384 + cc])       = make_float2(o00, o01);
                *reinterpret_cast<float2*>(&Cf[(size_t)(r + 8) * 384 + cc]) = make_float2(o10, o11);
            }
        }
    }
}

// ---------------------------------------------------------------------------
// Kernel 3: attention (round-12 structure), fp16 Q/K/V inputs.
// Thread = (rows i0 = tid>>2 and i0+32, quarter cq = tid&3). block 128.
// ---------------------------------------------------------------------------
__global__ __launch_bounds__(128) void attn_kernel(const float* __restrict__ mask)
{
    __shared__ float qs [NTOK * DH];
    __shared__ float kss[NTOK * DH];
    __shared__ float vss[NTOK * DH];
    __shared__ float at [NTOK * 65];
    __shared__ float qn [NTOK];
    __shared__ float kn [NTOK];
    __shared__ float tbs[225];

    const int b   = blockIdx.x;
    const int h   = blockIdx.y;
    const int tid = threadIdx.x;
    const size_t base = (size_t)b * NTOK * CDIM + h * DH;

    for (int idx = tid; idx < 512; idx += 128) {
        int n = idx >> 3;
        int d = (idx & 7) << 2;
        size_t ga = base + (size_t)n * CDIM + d;
        {
            uint2 v = *reinterpret_cast<const uint2*>(&g_Qh[ga]);
            float2 f0 = __half22float2(*reinterpret_cast<__half2*>(&v.x));
            float2 f1 = __half22float2(*reinterpret_cast<__half2*>(&v.y));
            *reinterpret_cast<float4*>(&qs[n * DH + d]) = make_float4(f0.x, f0.y, f1.x, f1.y);
        }
        {
            uint2 v = *reinterpret_cast<const uint2*>(&g_Kh[ga]);
            float2 f0 = __half22float2(*reinterpret_cast<__half2*>(&v.x));
            float2 f1 = __half22float2(*reinterpret_cast<__half2*>(&v.y));
            *reinterpret_cast<float4*>(&kss[n * DH + d]) = make_float4(f0.x, f0.y, f1.x, f1.y);
        }
        {
            uint2 v = *reinterpret_cast<const uint2*>(&g_Vh[ga]);
            float2 f0 = __half22float2(*reinterpret_cast<__half2*>(&v.x));
            float2 f1 = __half22float2(*reinterpret_cast<__half2*>(&v.y));
            *reinterpret_cast<float4*>(&vss[n * DH + d]) = make_float4(f0.x, f0.y, f1.x, f1.y);
        }
    }
    for (int i = tid; i < 225; i += 128) tbs[i] = g_tb[i * NHEADS + h];
    // pre-stage mask into at
    {
        const float4* mp = reinterpret_cast<const float4*>(mask + (size_t)b * 4096);
        for (int idx = tid; idx < 1024; idx += 128) {
            float4 mv = mp[idx];
            int f = idx << 2;
            int i = f >> 6, j = f & 63;
            at[i * 65 + j]     = mv.x;
            at[i * 65 + j + 1] = mv.y;
            at[i * 65 + j + 2] = mv.z;
            at[i * 65 + j + 3] = mv.w;
        }
    }
    const float ls = g_ls[h];
    __syncthreads();

    // norms
    {
        const float* src = (tid < 64) ? qs : kss;
        int i = (tid < 64) ? tid : (tid - 64);
        const ulonglong2* p = reinterpret_cast<const ulonglong2*>(&src[i * DH]);
        ull a0 = 0ull, a1 = 0ull;
        #pragma unroll
        for (int u = 0; u < 8; u++) {
            ulonglong2 v = p[u];
            a0 = fma2(v.x, v.x, a0);
            a1 = fma2(v.y, v.y, a1);
        }
        float2 s2 = upk2(add2(a0, a1));
        float nrm = sqrtf(s2.x + s2.y);
        if (tid < 64) qn[i] = nrm; else kn[i] = nrm;
    }
    __syncthreads();

    const int i0 = tid >> 2;
    const int i1 = i0 + 32;
    const int cq = tid & 3;

    // logits: 2 rows x 16 cols per thread, skewed K loads
    {
        ull q0[16], q1[16];
        {
            const ulonglong2* p0 = reinterpret_cast<const ulonglong2*>(&qs[i0 * DH]);
            const ulonglong2* p1 = reinterpret_cast<const ulonglong2*>(&qs[i1 * DH]);
            #pragma unroll
            for (int u = 0; u < 8; u++) {
                ulonglong2 v0 = p0[u]; q0[2 * u] = v0.x; q0[2 * u + 1] = v0.y;
                ulonglong2 v1 = p1[u]; q1[2 * u] = v1.x; q1[2 * u + 1] = v1.y;
            }
        }
        const float qn0 = qn[i0], qn1 = qn[i1];
        const int r0 = i0 >> 3, c0 = i0 & 7;
        const int r1 = i1 >> 3, c1 = i1 & 7;
        const int sk = cq * 2;

        #pragma unroll 4
        for (int jj = 0; jj < 16; jj++) {
            const int j = cq * 16 + jj;
            const ulonglong2* kp = reinterpret_cast<const ulonglong2*>(&kss[j * DH]);
            ull a0 = 0ull, a1 = 0ull, c0a = 0ull, c1a = 0ull;
            #pragma unroll
            for (int s = 0; s < 8; s++) {
                const int u = (s + sk) & 7;
                ulonglong2 kv = kp[u];
                a0  = fma2(q0[2 * u],     kv.x, a0);
                a1  = fma2(q0[2 * u + 1], kv.y, a1);
                c0a = fma2(q1[2 * u],     kv.x, c0a);
                c1a = fma2(q1[2 * u + 1], kv.y, c1a);
            }
            float2 sa = upk2(add2(a0, a1));
            float2 sb = upk2(add2(c0a, c1a));
            float dot0 = sa.x + sa.y;
            float dot1 = sb.x + sb.y;
            const float knj = kn[j];
            const int rj = j >> 3, cj = j & 7;
            int idx0 = ((r0 - rj) + 7) * 15 + (c0 - cj) + 7;
            int idx1 = ((r1 - rj) + 7) * 15 + (c1 - cj) + 7;
            float f0 = __fdividef(ls, fmaxf(qn0 * knj, 1e-6f));
            float f1 = __fdividef(ls, fmaxf(qn1 * knj, 1e-6f));
            at[i0 * 65 + j] = dot0 * f0 + tbs[idx0] + at[i0 * 65 + j];
            at[i1 * 65 + j] = dot1 * f1 + tbs[idx1] + at[i1 * 65 + j];
        }
    }
    __syncthreads();

    // softmax per row
    if (tid < 64) {
        float* row = &at[tid * 65];
        float m = row[0];
        #pragma unroll 8
        for (int j = 1; j < 64; j++) m = fmaxf(m, row[j]);
        float s = 0.f;
        #pragma unroll 8
        for (int j = 0; j < 64; j++) { float e = __expf(row[j] - m); row[j] = e; s += e; }
        float inv = 1.0f / s;
        #pragma unroll 8
        for (int j = 0; j < 64; j++) row[j] *= inv;
    }
    __syncthreads();

    // AV: 2 rows x 8 d-cols per thread
    {
        const int d0 = cq * 8;
        ull acc0[4], acc1[4];
        #pragma unroll
        for (int u = 0; u < 4; u++) { acc0[u] = 0ull; acc1[u] = 0ull; }
        const float* pr0 = &at[i0 * 65];
        const float* pr1 = &at[i1 * 65];
        #pragma unroll 4
        for (int j = 0; j < 64; j++) {
            const ulonglong2* vp = reinterpret_cast<const ulonglong2*>(&vss[j * DH + d0]);
            ulonglong2 v = vp[0], v2 = vp[1];
            float p0 = pr0[j], p1 = pr1[j];
            ull pp0 = pk2(p0, p0);
            ull pp1 = pk2(p1, p1);
            acc0[0] = fma2(pp0, v.x,  acc0[0]);
            acc0[1] = fma2(pp0, v.y,  acc0[1]);
            acc0[2] = fma2(pp0, v2.x, acc0[2]);
            acc0[3] = fma2(pp0, v2.y, acc0[3]);
            acc1[0] = fma2(pp1, v.x,  acc1[0]);
            acc1[1] = fma2(pp1, v.y,  acc1[1]);
            acc1[2] = fma2(pp1, v2.x, acc1[2]);
            acc1[3] = fma2(pp1, v2.y, acc1[3]);
        }
        #pragma unroll
        for (int rr = 0; rr < 2; rr++) {
            ull* ac = rr ? acc1 : acc0;
            int  ii = rr ? i1 : i0;
            __align__(16) __half hh[8], ll[8];
            #pragma unroll
            for (int u = 0; u < 4; u++) {
                float2 f = upk2(ac[u]);
                __half h0 = __float2half_rn(f.x);
                __half h1 = __float2half_rn(f.y);
                hh[2 * u]     = h0;
                hh[2 * u + 1] = h1;
                ll[2 * u]     = __float2half_rn(f.x - __half2float(h0));
                ll[2 * u + 1] = __float2half_rn(f.y - __half2float(h1));
            }
            size_t ob = (size_t)(b * NTOK + ii) * CDIM + h * DH + d0;
            *reinterpret_cast<uint4*>(&g_Ahi[ob]) = *reinterpret_cast<uint4*>(hh);
            *reinterpret_cast<uint4*>(&g_Alo[ob]) = *reinterpret_cast<uint4*>(ll);
        }
    }
}

// ---------------------------------------------------------------------------
// Launch
// ---------------------------------------------------------------------------
extern "C" void kernel_launch(void* const* d_in, const int* in_sizes, int n_in,
                              void* d_out, int out_size)
{
    (void)in_sizes; (void)n_in; (void)out_size;
    const float* x     = (const float*)d_in[0];
    const float* mask  = (const float*)d_in[1];
    const float* wq    = (const float*)d_in[2];
    const float* bq    = (const float*)d_in[3];
    const float* wk    = (const float*)d_in[4];
    const float* wv    = (const float*)d_in[5];
    const float* bv    = (const float*)d_in[6];
    const float* cw1   = (const float*)d_in[7];
    const float* cb1   = (const float*)d_in[8];
    const float* cw2   = (const float*)d_in[9];
    const float* cb2   = (const float*)d_in[10];
    const float* tau   = (const float*)d_in[11];
    const float* wproj = (const float*)d_in[12];
    const float* bproj = (const float*)d_in[13];
    float* out = (float*)d_out;

    float *pBcat;
    __half *pQh, *pKh, *pVh, *pAhi, *pAlo, *pW;
    cudaGetSymbolAddress((void**)&pQh,   g_Qh);
    cudaGetSymbolAddress((void**)&pKh,   g_Kh);
    cudaGetSymbolAddress((void**)&pVh,   g_Vh);
    cudaGetSymbolAddress((void**)&pBcat, g_bcat);
    cudaGetSymbolAddress((void**)&pAhi,  g_Ahi);
    cudaGetSymbolAddress((void**)&pAlo,  g_Alo);
    cudaGetSymbolAddress((void**)&pW,    g_W);

    cudaFuncSetAttribute(gemm_cp_kernel, cudaFuncAttributeMaxDynamicSharedMemorySize,
                         GEMM_SMEM);

    const int xn4 = MROWS * CDIM / 4;
    const int PROJ_OFF = CDIM * 1152;

    convert_split_kernel<<<(xn4 + 255) / 256, 256>>>(x, pAhi, pAlo, xn4);
    w_fp16_kernel<<<144, 256>>>(wq, pW, 1152, 0);
    w_fp16_kernel<<<144, 256>>>(wk, pW, 1152, 384);
    w_fp16_kernel<<<144, 256>>>(wv, pW, 1152, 768);
    bias_cat_kernel<<<5, 256>>>(bq, bv);

    gemm_cp_kernel<<<dim3(9, MROWS / 128), 256, GEMM_SMEM>>>(
        pAhi, pAlo, pW, pBcat, pQh, pKh, pVh, 1152, 1);

    cpb_kernel<<<225, 128>>>(cw1, cb1, cw2, cb2, tau);
    attn_kernel<<<dim3(NWIN, NHEADS), 128>>>(mask);

    w_fp16_kernel<<<144, 256>>>(wproj, pW + PROJ_OFF, 384, 0);
    gemm_cp_kernel<<<dim3(3, MROWS / 128), 256, GEMM_SMEM>>>(
        pAhi, pAlo, pW + PROJ_OFF, bproj, out, nullptr, nullptr, 384, 0);
}

// round 16
// speedup vs baseline: 1.6676x; 1.4460x over previous
#include <cuda_runtime.h>
#include <cuda_fp16.h>
#include <cstdint>
#include <math.h>

#define NHEADS 12
#define NWIN   1152
#define NTOK   64
#define CDIM   384
#define DH     32
#define MROWS  (NWIN * NTOK)   // 73728

typedef unsigned long long ull;

// ---------------------------------------------------------------------------
// Device-global scratch
// ---------------------------------------------------------------------------
__device__ __half g_Qh[MROWS * CDIM];
__device__ __half g_Kh[MROWS * CDIM];
__device__ __half g_Vh[MROWS * CDIM];
__device__ float g_tb[225 * NHEADS];
__device__ float g_ls[NHEADS];
__device__ float g_bcat[3 * CDIM];

__device__ __half g_Ahi[MROWS * CDIM];
__device__ __half g_Alo[MROWS * CDIM];
__device__ __half g_W[CDIM * 1536];

// ---------------------------------------------------------------------------
// helpers
// ---------------------------------------------------------------------------
__device__ __forceinline__ uint32_t smem_u32(const void* p)
{
    uint32_t a;
    asm("{ .reg .u64 t; cvta.to.shared.u64 t, %1; cvt.u32.u64 %0, t; }" : "=r"(a) : "l"(p));
    return a;
}
__device__ __forceinline__ void cp16(uint32_t dst, const void* src)
{
    asm volatile("cp.async.cg.shared.global [%0], [%1], 16;" :: "r"(dst), "l"(src));
}
#define CP_COMMIT() asm volatile("cp.async.commit_group;" ::: "memory")
#define CP_WAIT1()  asm volatile("cp.async.wait_group 1;" ::: "memory")
#define CP_WAIT0()  asm volatile("cp.async.wait_group 0;" ::: "memory")

__device__ __forceinline__ void ldsm_x4(uint32_t r[4], uint32_t addr)
{
    asm volatile("ldmatrix.sync.aligned.m8n8.x4.shared.b16 {%0,%1,%2,%3}, [%4];"
                 : "=r"(r[0]), "=r"(r[1]), "=r"(r[2]), "=r"(r[3]) : "r"(addr));
}
__device__ __forceinline__ void ldsm_x4_t(uint32_t r[4], uint32_t addr)
{
    asm volatile("ldmatrix.sync.aligned.m8n8.x4.trans.shared.b16 {%0,%1,%2,%3}, [%4];"
                 : "=r"(r[0]), "=r"(r[1]), "=r"(r[2]), "=r"(r[3]) : "r"(addr));
}
__device__ __forceinline__ void mma_f16(float c[4], const uint32_t a[4], const uint32_t b[2])
{
    asm volatile(
        "mma.sync.aligned.m16n8k16.row.col.f32.f16.f16.f32 "
        "{%0,%1,%2,%3},{%4,%5,%6,%7},{%8,%9},{%0,%1,%2,%3};"
        : "+f"(c[0]), "+f"(c[1]), "+f"(c[2]), "+f"(c[3])
        : "r"(a[0]), "r"(a[1]), "r"(a[2]), "r"(a[3]), "r"(b[0]), "r"(b[1]));
}

// ---------------------------------------------------------------------------
// Kernel 0a: fp32 -> (fp16 hi, fp16 lo) split
// ---------------------------------------------------------------------------
__global__ void convert_split_kernel(const float* __restrict__ src,
                                     __half* __restrict__ hi,
                                     __half* __restrict__ lo, int n4)
{
    int i = blockIdx.x * blockDim.x + threadIdx.x;
    if (i >= n4) return;
    float4 v = reinterpret_cast<const float4*>(src)[i];
    float vv[4] = {v.x, v.y, v.z, v.w};
    __align__(8) __half h[4], l[4];
    #pragma unroll
    for (int j = 0; j < 4; j++) {
        h[j] = __float2half_rn(vv[j]);
        l[j] = __float2half_rn(vv[j] - __half2float(h[j]));
    }
    reinterpret_cast<uint2*>(hi)[i] = *reinterpret_cast<uint2*>(h);
    reinterpret_cast<uint2*>(lo)[i] = *reinterpret_cast<uint2*>(l);
}

// ---------------------------------------------------------------------------
// Kernel 0b: W[k][n] fp32 -> fp16 plane at column offset
// ---------------------------------------------------------------------------
__global__ void w_fp16_kernel(const float* __restrict__ src,
                              __half* __restrict__ dst,
                              int ncols, int coloff)
{
    int i = blockIdx.x * blockDim.x + threadIdx.x;
    if (i >= 36864) return;
    int k  = i / 96;
    int n4 = (i % 96) * 4;
    float4 v = *reinterpret_cast<const float4*>(&src[(size_t)k * 384 + n4]);
    __align__(8) __half h[4];
    h[0] = __float2half_rn(v.x);
    h[1] = __float2half_rn(v.y);
    h[2] = __float2half_rn(v.z);
    h[3] = __float2half_rn(v.w);
    size_t o = (size_t)k * ncols + coloff + n4;
    *reinterpret_cast<uint2*>(&dst[o]) = *reinterpret_cast<uint2*>(h);
}

__global__ void bias_cat_kernel(const float* __restrict__ bq, const float* __restrict__ bv)
{
    int i = blockIdx.x * blockDim.x + threadIdx.x;
    if (i >= 1152) return;
    g_bcat[i] = (i < 384) ? bq[i] : ((i < 768) ? 0.f : bv[i - 768]);
}

// ---------------------------------------------------------------------------
// Kernel 1: continuous position bias MLP (stores 16*sigmoid directly)
// ---------------------------------------------------------------------------
__global__ void cpb_kernel(const float* __restrict__ w1, const float* __restrict__ b1,
                           const float* __restrict__ w2, const float* __restrict__ b2,
                           const float* __restrict__ tau)
{
    __shared__ float red[128][12];
    const int m   = blockIdx.x;
    const int tid = threadIdx.x;
    const int ai  = m / 15;
    const int bi  = m % 15;

    float x0 = (float)(bi - 7) * (8.0f / 7.0f);
    float x1 = (float)(ai - 7) * (8.0f / 7.0f);
    float s0 = (x0 > 0.f) ? 1.f : ((x0 < 0.f) ? -1.f : 0.f);
    float s1 = (x1 > 0.f) ? 1.f : ((x1 < 0.f) ? -1.f : 0.f);
    float v0 = s0 * log2f(fabsf(x0) + 1.0f) * (1.0f / 3.0f);
    float v1 = s1 * log2f(fabsf(x1) + 1.0f) * (1.0f / 3.0f);

    float p[NHEADS];
    #pragma unroll
    for (int h = 0; h < NHEADS; h++) p[h] = 0.f;

    for (int c = tid; c < 512; c += 128) {
        float hv = v0 * w1[c] + v1 * w1[512 + c] + b1[c];
        hv = fmaxf(hv, 0.0f);
        #pragma unroll
        for (int h = 0; h < NHEADS; h++) p[h] += hv * w2[c * NHEADS + h];
    }
    #pragma unroll
    for (int h = 0; h < NHEADS; h++) red[tid][h] = p[h];
    __syncthreads();

    if (tid < NHEADS) {
        float s = 0.f;
        for (int t2 = 0; t2 < 128; t2++) s += red[t2][tid];
        float v = s + b2[tid];
        g_tb[m * NHEADS + tid] = 16.0f / (1.0f + expf(-v));
        if (m == 0) g_ls[tid] = fmaxf(tau[tid] + 2.302585092994046f, 0.01f);
    }
}

// ---------------------------------------------------------------------------
// Kernel 2: 3-stage cp.async fp16 GEMM (unchanged from round 14)
// ---------------------------------------------------------------------------
#define A_BYTES 18432
#define B_BYTES 17408
#define STG_BYTES (A_BYTES + B_BYTES)
#define GEMM_SMEM (3 * STG_BYTES)

__global__ __launch_bounds__(256, 2) void gemm_cp_kernel(
    const __half* __restrict__ Ahi, const __half* __restrict__ Alo,
    const __half* __restrict__ W,
    const float* __restrict__ bias,
    void* C0, void* C1, void* C2, int Ntot, int half_out)
{
    extern __shared__ __align__(128) char smem[];
    const uint32_t sb = smem_u32(smem);
    const int tid  = threadIdx.x;
    const int lane = tid & 31;
    const int warp = tid >> 5;
    const int wm   = warp >> 2;
    const int wn   = warp & 3;
    const int rb   = blockIdx.y * 128;
    const int cb   = blockIdx.x * 128;
    const int gid  = cb / 384;
    void* C = (gid == 0) ? C0 : ((gid == 1) ? C1 : C2);

    const int g  = lane >> 3;
    const int lr = lane & 7;
    const int a_row  = wm * 64 + lr + (g & 1) * 8;
    const int a_col  = (g >> 1) * 8;
    const int b_krow = lr + (g & 1) * 8;
    const int b_ncol = wn * 32 + (g >> 1) * 8;

    float acc[4][4][4];
    #pragma unroll
    for (int mi = 0; mi < 4; mi++)
        #pragma unroll
        for (int ni = 0; ni < 4; ni++)
            #pragma unroll
            for (int q = 0; q < 4; q++) acc[mi][ni][q] = 0.f;

    auto stage = [&](int c, int buf) {
        const int kl = (c % 6) * 64;
        const __half* pA = (c < 6) ? Ahi : Alo;
        const uint32_t st = sb + buf * STG_BYTES;
        #pragma unroll
        for (int i = 0; i < 4; i++) {
            int id = tid + i * 256;
            int r  = id >> 3;
            int cc = id & 7;
            cp16(st + r * 144 + cc * 16,
                 &pA[(size_t)(rb + r) * 384 + kl + cc * 8]);
        }
        #pragma unroll
        for (int i = 0; i < 4; i++) {
            int id = tid + i * 256;
            int r  = id >> 4;
            int cc = id & 15;
            cp16(st + A_BYTES + r * 272 + cc * 16,
                 &W[(size_t)(kl + r) * Ntot + cb + cc * 8]);
        }
    };

    stage(0, 0); CP_COMMIT();
    stage(1, 1); CP_COMMIT();

    for (int c = 0; c < 12; c++) {
        if (c < 11) CP_WAIT1(); else CP_WAIT0();
        __syncthreads();
        if (c + 2 < 12) { stage(c + 2, (c + 2) % 3); CP_COMMIT(); }

        const uint32_t sA = sb + (c % 3) * STG_BYTES;
        const uint32_t sB = sA + A_BYTES;
        #pragma unroll
        for (int ks = 0; ks < 4; ks++) {
            uint32_t af[4][4];
            #pragma unroll
            for (int mi = 0; mi < 4; mi++)
                ldsm_x4(af[mi], sA + ((a_row + mi * 16) * 72 + ks * 16 + a_col) * 2);
            uint32_t bf_[2][4];
            #pragma unroll
            for (int nt = 0; nt < 2; nt++)
                ldsm_x4_t(bf_[nt], sB + ((ks * 16 + b_krow) * 136 + b_ncol + nt * 16) * 2);
            #pragma unroll
            for (int mi = 0; mi < 4; mi++)
                #pragma unroll
                for (int ni = 0; ni < 4; ni++)
                    mma_f16(acc[mi][ni], af[mi], &bf_[ni >> 1][(ni & 1) * 2]);
        }
    }

    #pragma unroll
    for (int mi = 0; mi < 4; mi++) {
        #pragma unroll
        for (int ni = 0; ni < 4; ni++) {
            int r    = rb + wm * 64 + mi * 16 + (lane >> 2);
            int ccat = cb + wn * 32 + ni * 8 + (lane & 3) * 2;
            int cc   = ccat - gid * 384;
            float b0 = bias[ccat];
            float b1 = bias[ccat + 1];
            float o00 = acc[mi][ni][0] + b0, o01 = acc[mi][ni][1] + b1;
            float o10 = acc[mi][ni][2] + b0, o11 = acc[mi][ni][3] + b1;
            if (half_out) {
                __half* Ch = (__half*)C;
                *reinterpret_cast<__half2*>(&Ch[(size_t)r * 384 + cc])       = __floats2half2_rn(o00, o01);
                *reinterpret_cast<__half2*>(&Ch[(size_t)(r + 8) * 384 + cc]) = __floats2half2_rn(o10, o11);
            } else {
                float* Cf = (float*)C;
                *reinterpret_cast<float2*>(&Cf[(size_t)r * 384 + cc])       = make_float2(o00, o01);
                *reinterpret_cast<float2*>(&Cf[(size_t)(r + 8) * 384 + cc]) = make_float2(o10, o11);
            }
        }
    }
}

// ---------------------------------------------------------------------------
// Kernel 3: tensor-core attention. 4 warps, warp w owns rows w*16..w*16+15.
// S in accum regs -> fixup -> register softmax (shfl over lanes xor 1,2)
// -> P repacked to A-frags (hi+lo fp16 split) -> AV via mma. 2 barriers.
// grid (1152,12), block 128.
// ---------------------------------------------------------------------------
__global__ __launch_bounds__(128) void attn_tc_kernel(const float* __restrict__ mask)
{
    __shared__ __align__(16) __half qsm[64 * 40];
    __shared__ __align__(16) __half ksm[64 * 40];
    __shared__ __align__(16) __half vsm[64 * 40];
    __shared__ float msk[64 * 65];
    __shared__ float tbs[225];
    __shared__ float qn[64];
    __shared__ float kn[64];

    const int b = blockIdx.x, h = blockIdx.y, tid = threadIdx.x;
    const int warp = tid >> 5, lane = tid & 31;

    // stage Q/K/V fp16 (rows of 32 halves -> smem rows of 40)
    const size_t base = (size_t)b * NTOK * CDIM + h * DH;
    for (int idx = tid; idx < 256; idx += 128) {
        int n = idx >> 2, ch = (idx & 3) * 8;
        size_t ga = base + (size_t)n * CDIM + ch;
        *reinterpret_cast<uint4*>(&qsm[n * 40 + ch]) = *reinterpret_cast<const uint4*>(&g_Qh[ga]);
        *reinterpret_cast<uint4*>(&ksm[n * 40 + ch]) = *reinterpret_cast<const uint4*>(&g_Kh[ga]);
        *reinterpret_cast<uint4*>(&vsm[n * 40 + ch]) = *reinterpret_cast<const uint4*>(&g_Vh[ga]);
    }
    for (int i = tid; i < 225; i += 128) tbs[i] = g_tb[i * NHEADS + h];
    {
        const float4* mp = reinterpret_cast<const float4*>(mask + (size_t)b * 4096);
        for (int idx = tid; idx < 1024; idx += 128) {
            float4 mv = mp[idx];
            int f = idx << 2;
            int i = f >> 6, j = f & 63;
            msk[i * 65 + j]     = mv.x;
            msk[i * 65 + j + 1] = mv.y;
            msk[i * 65 + j + 2] = mv.z;
            msk[i * 65 + j + 3] = mv.w;
        }
    }
    const float ls = g_ls[h];
    __syncthreads();

    // norms from fp16 smem
    {
        int t = (tid < 64) ? tid : (tid - 64);
        const __half2* p = reinterpret_cast<const __half2*>((tid < 64) ? &qsm[t * 40] : &ksm[t * 40]);
        float s = 0.f;
        #pragma unroll
        for (int u = 0; u < 16; u++) {
            float2 f = __half22float2(p[u]);
            s += f.x * f.x + f.y * f.y;
        }
        if (tid < 64) qn[t] = sqrtf(s); else kn[t] = sqrtf(s);
    }
    __syncthreads();

    const int rw = warp * 16;
    const int g  = lane >> 3, lr = lane & 7;
    const uint32_t qsb = smem_u32(qsm), ksb = smem_u32(ksm), vsb = smem_u32(vsm);

    // Q fragments (2 k-steps of 16 d)
    uint32_t aq[2][4];
    #pragma unroll
    for (int ks = 0; ks < 2; ks++)
        ldsm_x4(aq[ks], qsb + (uint32_t)(((rw + lr + (g & 1) * 8) * 40 + ks * 16 + (g >> 1) * 8) * 2));

    // S = Q @ K^T  (8 n-tiles of 8 cols)
    float c[8][4];
    #pragma unroll
    for (int nt = 0; nt < 8; nt++)
        #pragma unroll
        for (int q = 0; q < 4; q++) c[nt][q] = 0.f;

    #pragma unroll
    for (int jt = 0; jt < 4; jt++) {
        #pragma unroll
        for (int ks = 0; ks < 2; ks++) {
            uint32_t kb[4];
            // non-trans ldsm over K[j][d]: rows = n(j), cols = k(d)
            ldsm_x4(kb, ksb + (uint32_t)(((jt * 16 + lr + (g >> 1) * 8) * 40 + ks * 16 + (g & 1) * 8) * 2));
            mma_f16(c[jt * 2],     aq[ks], &kb[0]);
            mma_f16(c[jt * 2 + 1], aq[ks], &kb[2]);
        }
    }

    // fix-up: cosine scale + cpb bias + mask
    const int r   = lane >> 2;
    const int cc2 = (lane & 3) * 2;
    const int i0 = rw + r, i1 = i0 + 8;
    const float qn0 = qn[i0], qn1 = qn[i1];
    const int ri0 = i0 >> 3, ci0 = i0 & 7;
    const int ri1 = i1 >> 3, ci1 = i1 & 7;

    #pragma unroll
    for (int nt = 0; nt < 8; nt++) {
        #pragma unroll
        for (int q = 0; q < 2; q++) {
            int j = nt * 8 + cc2 + q;
            float knj = kn[j];
            int rj = j >> 3, cj = j & 7;
            float b0 = tbs[((ri0 - rj) + 7) * 15 + (ci0 - cj) + 7] + msk[i0 * 65 + j];
            float b1 = tbs[((ri1 - rj) + 7) * 15 + (ci1 - cj) + 7] + msk[i1 * 65 + j];
            c[nt][q]     = c[nt][q]     * __fdividef(ls, fmaxf(qn0 * knj, 1e-6f)) + b0;
            c[nt][q + 2] = c[nt][q + 2] * __fdividef(ls, fmaxf(qn1 * knj, 1e-6f)) + b1;
        }
    }

    // register softmax (rows i0 and i1; cols spread over lanes xor 1,2)
    {
        float mx0 = -1e30f, mx1 = -1e30f;
        #pragma unroll
        for (int nt = 0; nt < 8; nt++) {
            mx0 = fmaxf(mx0, fmaxf(c[nt][0], c[nt][1]));
            mx1 = fmaxf(mx1, fmaxf(c[nt][2], c[nt][3]));
        }
        mx0 = fmaxf(mx0, __shfl_xor_sync(0xffffffffu, mx0, 1));
        mx0 = fmaxf(mx0, __shfl_xor_sync(0xffffffffu, mx0, 2));
        mx1 = fmaxf(mx1, __shfl_xor_sync(0xffffffffu, mx1, 1));
        mx1 = fmaxf(mx1, __shfl_xor_sync(0xffffffffu, mx1, 2));
        float s0 = 0.f, s1 = 0.f;
        #pragma unroll
        for (int nt = 0; nt < 8; nt++) {
            c[nt][0] = __expf(c[nt][0] - mx0); s0 += c[nt][0];
            c[nt][1] = __expf(c[nt][1] - mx0); s0 += c[nt][1];
            c[nt][2] = __expf(c[nt][2] - mx1); s1 += c[nt][2];
            c[nt][3] = __expf(c[nt][3] - mx1); s1 += c[nt][3];
        }
        s0 += __shfl_xor_sync(0xffffffffu, s0, 1);
        s0 += __shfl_xor_sync(0xffffffffu, s0, 2);
        s1 += __shfl_xor_sync(0xffffffffu, s1, 1);
        s1 += __shfl_xor_sync(0xffffffffu, s1, 2);
        float inv0 = 1.0f / s0, inv1 = 1.0f / s1;
        #pragma unroll
        for (int nt = 0; nt < 8; nt++) {
            c[nt][0] *= inv0; c[nt][1] *= inv0;
            c[nt][2] *= inv1; c[nt][3] *= inv1;
        }
    }

    // repack P into A-fragments: hi + lo fp16 split (register-only, C≡A layout)
    uint32_t ap[4][4], apl[4][4];
    #pragma unroll
    for (int kt = 0; kt < 4; kt++) {
        #pragma unroll
        for (int half_idx = 0; half_idx < 4; half_idx++) {
            // half_idx: 0 -> (c[2kt][0],c[2kt][1]); 1 -> (c[2kt][2],c[2kt][3]);
            //           2 -> (c[2kt+1][0],c[2kt+1][1]); 3 -> (c[2kt+1][2],c[2kt+1][3])
            int nt = kt * 2 + (half_idx >> 1);
            int q0 = (half_idx & 1) * 2;
            float v0 = c[nt][q0], v1 = c[nt][q0 + 1];
            __half h0 = __float2half_rn(v0);
            __half h1 = __float2half_rn(v1);
            __half l0 = __float2half_rn(v0 - __half2float(h0));
            __half l1 = __float2half_rn(v1 - __half2float(h1));
            __half2 hh = __halves2half2(h0, h1);
            __half2 lh = __halves2half2(l0, l1);
            ap[kt][half_idx]  = *reinterpret_cast<uint32_t*>(&hh);
            apl[kt][half_idx] = *reinterpret_cast<uint32_t*>(&lh);
        }
    }

    // D = P @ V  (4 n-tiles of 8 d-cols)
    float dacc[4][4];
    #pragma unroll
    for (int nt = 0; nt < 4; nt++)
        #pragma unroll
        for (int q = 0; q < 4; q++) dacc[nt][q] = 0.f;

    #pragma unroll
    for (int kt = 0; kt < 4; kt++) {
        #pragma unroll
        for (int vt = 0; vt < 2; vt++) {
            uint32_t vb[4];
            // trans ldsm over V[j][d]: rows = k(j), cols = n(d)  (GEMM-B pattern)
            ldsm_x4_t(vb, vsb + (uint32_t)(((kt * 16 + lr + (g & 1) * 8) * 40 + vt * 16 + (g >> 1) * 8) * 2));
            mma_f16(dacc[vt * 2],     ap[kt],  &vb[0]);
            mma_f16(dacc[vt * 2 + 1], ap[kt],  &vb[2]);
            mma_f16(dacc[vt * 2],     apl[kt], &vb[0]);
            mma_f16(dacc[vt * 2 + 1], apl[kt], &vb[2]);
        }
    }

    // write AO as fp16 hi/lo split
    #pragma unroll
    for (int nt = 0; nt < 4; nt++) {
        int col = h * DH + nt * 8 + cc2;
        #pragma unroll
        for (int rr = 0; rr < 2; rr++) {
            int ii = rr ? i1 : i0;
            float v0 = dacc[nt][rr * 2], v1 = dacc[nt][rr * 2 + 1];
            __half h0 = __float2half_rn(v0);
            __half h1 = __float2half_rn(v1);
            __half l0 = __float2half_rn(v0 - __half2float(h0));
            __half l1 = __float2half_rn(v1 - __half2float(h1));
            size_t ob = (size_t)(b * NTOK + ii) * CDIM + col;
            *reinterpret_cast<__half2*>(&g_Ahi[ob]) = __halves2half2(h0, h1);
            *reinterpret_cast<__half2*>(&g_Alo[ob]) = __halves2half2(l0, l1);
        }
    }
}

// ---------------------------------------------------------------------------
// Launch
// ---------------------------------------------------------------------------
extern "C" void kernel_launch(void* const* d_in, const int* in_sizes, int n_in,
                              void* d_out, int out_size)
{
    (void)in_sizes; (void)n_in; (void)out_size;
    const float* x     = (const float*)d_in[0];
    const float* mask  = (const float*)d_in[1];
    const float* wq    = (const float*)d_in[2];
    const float* bq    = (const float*)d_in[3];
    const float* wk    = (const float*)d_in[4];
    const float* wv    = (const float*)d_in[5];
    const float* bv    = (const float*)d_in[6];
    const float* cw1   = (const float*)d_in[7];
    const float* cb1   = (const float*)d_in[8];
    const float* cw2   = (const float*)d_in[9];
    const float* cb2   = (const float*)d_in[10];
    const float* tau   = (const float*)d_in[11];
    const float* wproj = (const float*)d_in[12];
    const float* bproj = (const float*)d_in[13];
    float* out = (float*)d_out;

    float *pBcat;
    __half *pQh, *pKh, *pVh, *pAhi, *pAlo, *pW;
    cudaGetSymbolAddress((void**)&pQh,   g_Qh);
    cudaGetSymbolAddress((void**)&pKh,   g_Kh);
    cudaGetSymbolAddress((void**)&pVh,   g_Vh);
    cudaGetSymbolAddress((void**)&pBcat, g_bcat);
    cudaGetSymbolAddress((void**)&pAhi,  g_Ahi);
    cudaGetSymbolAddress((void**)&pAlo,  g_Alo);
    cudaGetSymbolAddress((void**)&pW,    g_W);

    cudaFuncSetAttribute(gemm_cp_kernel, cudaFuncAttributeMaxDynamicSharedMemorySize,
                         GEMM_SMEM);

    const int xn4 = MROWS * CDIM / 4;
    const int PROJ_OFF = CDIM * 1152;

    convert_split_kernel<<<(xn4 + 255) / 256, 256>>>(x, pAhi, pAlo, xn4);
    w_fp16_kernel<<<144, 256>>>(wq, pW, 1152, 0);
    w_fp16_kernel<<<144, 256>>>(wk, pW, 1152, 384);
    w_fp16_kernel<<<144, 256>>>(wv, pW, 1152, 768);
    bias_cat_kernel<<<5, 256>>>(bq, bv);

    gemm_cp_kernel<<<dim3(9, MROWS / 128), 256, GEMM_SMEM>>>(
        pAhi, pAlo, pW, pBcat, pQh, pKh, pVh, 1152, 1);

    cpb_kernel<<<225, 128>>>(cw1, cb1, cw2, cb2, tau);
    attn_tc_kernel<<<dim3(NWIN, NHEADS), 128>>>(mask);

    w_fp16_kernel<<<144, 256>>>(wproj, pW + PROJ_OFF, 384, 0);
    gemm_cp_kernel<<<dim3(3, MROWS / 128), 256, GEMM_SMEM>>>(
        pAhi, pAlo, pW + PROJ_OFF, bproj, out, nullptr, nullptr, 384, 0);
}